// round 4
// baseline (speedup 1.0000x reference)
#include <cuda_runtime.h>

// DCN CrossLayer closed form: out = x0 * a3 + (b0+b1+b2), with
//   d_l = dot(x0, w_l), c1 = dot(b0,w1), c2 = dot(b0+b1,w2),
//   a1 = 1+d0; s1 = a1*d1+c1; a2 = a1+s1; s2 = a2*d2+c2; a3 = a2+s2.
//
// Block-per-row-group: 256 threads, thread t owns float4 feature index t.
// w0/w1/w2/B live in registers (no per-row smem weight traffic).
// 2 rows per iteration, double-buffered reduction smem, prefetched x.

#define F_DIM 1024
#define F4    256          // float4 per row
#define ROWS_PER_BLOCK 8   // 4 iterations x 2 rows

__device__ __forceinline__ float dot4(float4 a, float4 b, float acc) {
    acc = fmaf(a.x, b.x, acc);
    acc = fmaf(a.y, b.y, acc);
    acc = fmaf(a.z, b.z, acc);
    return fmaf(a.w, b.w, acc);
}

__global__ void __launch_bounds__(256, 4)
cross_layer_kernel(const float4* __restrict__ x,
                   const float*  __restrict__ w,   // [3,1024]
                   const float*  __restrict__ b,   // [3,1024]
                   float4* __restrict__ out,
                   int n_rows)
{
    __shared__ float4 sbuf[2][2][8];   // [parity][row-in-pair][warp]

    const int tid  = threadIdx.x;
    const int lane = tid & 31;
    const int wid  = tid >> 5;

    // ---- Register-resident weights/bias at this thread's feature slice ----
    const float4* w0g = (const float4*)(w);
    const float4* w1g = (const float4*)(w + F_DIM);
    const float4* w2g = (const float4*)(w + 2 * F_DIM);
    const float4* b0g = (const float4*)(b);
    const float4* b1g = (const float4*)(b + F_DIM);
    const float4* b2g = (const float4*)(b + 2 * F_DIM);

    const float4 w0 = __ldg(&w0g[tid]);
    const float4 w1 = __ldg(&w1g[tid]);
    const float4 w2 = __ldg(&w2g[tid]);
    const float4 b0 = __ldg(&b0g[tid]);
    const float4 b1 = __ldg(&b1g[tid]);
    const float4 b2 = __ldg(&b2g[tid]);

    float4 b01, B;
    b01.x = b0.x + b1.x;  b01.y = b0.y + b1.y;
    b01.z = b0.z + b1.z;  b01.w = b0.w + b1.w;
    B.x = b01.x + b2.x;   B.y = b01.y + b2.y;
    B.z = b01.z + b2.z;   B.w = b01.w + b2.w;

    // ---- Block-wide c1 = dot(b0,w1), c2 = dot(b0+b1,w2) ----
    {
        float c1p = dot4(b0, w1, 0.0f);
        float c2p = dot4(b01, w2, 0.0f);
#pragma unroll
        for (int o = 16; o; o >>= 1) {
            c1p += __shfl_xor_sync(0xffffffffu, c1p, o);
            c2p += __shfl_xor_sync(0xffffffffu, c2p, o);
        }
        if (lane == 0) sbuf[0][0][wid] = make_float4(c1p, c2p, 0.0f, 0.0f);
    }
    __syncthreads();
    float c1 = 0.0f, c2 = 0.0f;
#pragma unroll
    for (int i = 0; i < 8; i++) {
        float4 v = sbuf[0][0][i];
        c1 += v.x; c2 += v.y;
    }
    __syncthreads();   // protect sbuf[0] before iteration 0 overwrites it

    // ---- Main loop: 2 rows per iteration ----
    const int row0 = blockIdx.x * ROWS_PER_BLOCK;
    const float4* __restrict__ xp = x + (size_t)row0 * F4 + tid;
    float4*       __restrict__ op = out + (size_t)row0 * F4 + tid;

    float4 xa = __ldg(xp);
    float4 xb = __ldg(xp + F4);

#pragma unroll
    for (int it = 0; it < ROWS_PER_BLOCK / 2; it++) {
        const int par = it & 1;

        // Prefetch next pair before the reduction latency chain.
        float4 xa_n, xb_n;
        if (it < ROWS_PER_BLOCK / 2 - 1) {
            xa_n = __ldg(xp + 2 * F4);
            xb_n = __ldg(xp + 3 * F4);
        }

        float pa0 = dot4(xa, w0, 0.0f);
        float pa1 = dot4(xa, w1, 0.0f);
        float pa2 = dot4(xa, w2, 0.0f);
        float pb0 = dot4(xb, w0, 0.0f);
        float pb1 = dot4(xb, w1, 0.0f);
        float pb2 = dot4(xb, w2, 0.0f);

#pragma unroll
        for (int o = 16; o; o >>= 1) {
            pa0 += __shfl_xor_sync(0xffffffffu, pa0, o);
            pa1 += __shfl_xor_sync(0xffffffffu, pa1, o);
            pa2 += __shfl_xor_sync(0xffffffffu, pa2, o);
            pb0 += __shfl_xor_sync(0xffffffffu, pb0, o);
            pb1 += __shfl_xor_sync(0xffffffffu, pb1, o);
            pb2 += __shfl_xor_sync(0xffffffffu, pb2, o);
        }
        if (lane == 0) {
            sbuf[par][0][wid] = make_float4(pa0, pa1, pa2, 0.0f);
            sbuf[par][1][wid] = make_float4(pb0, pb1, pb2, 0.0f);
        }
        __syncthreads();

        float da0 = 0.0f, da1 = 0.0f, da2 = 0.0f;
        float db0 = 0.0f, db1 = 0.0f, db2 = 0.0f;
#pragma unroll
        for (int i = 0; i < 8; i++) {
            float4 va = sbuf[par][0][i];
            float4 vb = sbuf[par][1][i];
            da0 += va.x; da1 += va.y; da2 += va.z;
            db0 += vb.x; db1 += vb.y; db2 += vb.z;
        }

        const float a1a = 1.0f + da0;
        const float s1a = fmaf(a1a, da1, c1);
        const float a2a = a1a + s1a;
        const float s2a = fmaf(a2a, da2, c2);
        const float a3a = a2a + s2a;

        const float a1b = 1.0f + db0;
        const float s1b = fmaf(a1b, db1, c1);
        const float a2b = a1b + s1b;
        const float s2b = fmaf(a2b, db2, c2);
        const float a3b = a2b + s2b;

        float4 oa, ob;
        oa.x = fmaf(xa.x, a3a, B.x);  oa.y = fmaf(xa.y, a3a, B.y);
        oa.z = fmaf(xa.z, a3a, B.z);  oa.w = fmaf(xa.w, a3a, B.w);
        ob.x = fmaf(xb.x, a3b, B.x);  ob.y = fmaf(xb.y, a3b, B.y);
        ob.z = fmaf(xb.z, a3b, B.z);  ob.w = fmaf(xb.w, a3b, B.w);

        op[0]  = oa;
        op[F4] = ob;

        xp += 2 * F4;
        op += 2 * F4;
        xa = xa_n;
        xb = xb_n;
    }
}

extern "C" void kernel_launch(void* const* d_in, const int* in_sizes, int n_in,
                              void* d_out, int out_size)
{
    const float4* x = (const float4*)d_in[0];
    const float*  w = (const float*)d_in[1];   // [3,1024,1]
    const float*  b = (const float*)d_in[2];   // [3,1024,1]
    float4* out = (float4*)d_out;

    const int n_rows = in_sizes[0] / F_DIM;                     // 16384
    const int grid   = (n_rows + ROWS_PER_BLOCK - 1) / ROWS_PER_BLOCK;  // 2048

    cross_layer_kernel<<<grid, 256>>>(x, w, b, out, n_rows);
}

// round 7
// speedup vs baseline: 1.2344x; 1.2344x over previous
#include <cuda_runtime.h>

// DCN CrossLayer closed form: out = x0 * a3 + (b0+b1+b2), with
//   d_l = dot(x0, w_l), c1 = dot(b0,w1), c2 = dot(b0+b1,w2),
//   a1 = 1+d0; s1 = a1*d1+c1; a2 = a1+s1; s2 = a2*d2+c2; a3 = a2+s2.
//
// Thread-owns-feature: 256 threads, thread t owns float4 chunk t of F=1024.
// w0/w1/w2/B register-resident. 4 rows per phase, 2 phases per block.
// 12 independent warp reductions done with ONE batched pairing butterfly
// (13 SHFLs total instead of 60).

#define F_DIM 1024
#define F4    256
#define RPI   4                      // rows per phase
#define ROWS_PER_BLOCK 8
#define FULL  0xffffffffu

__device__ __forceinline__ float dot4(float4 a, float4 b) {
    float acc = a.x * b.x;
    acc = fmaf(a.y, b.y, acc);
    acc = fmaf(a.z, b.z, acc);
    return fmaf(a.w, b.w, acc);
}

// One pairing step: accumulates 'a' onto lanes with (lane&off)==0 and 'b'
// onto lanes with (lane&off)!=0, one level deeper. 1 SHFL for 2 scalars.
__device__ __forceinline__ float pair_step(float a, float b, int off, int lane) {
    const bool hi = (lane & off) != 0;
    float keep = hi ? b : a;
    float send = hi ? a : b;
    return keep + __shfl_xor_sync(FULL, send, off);
}

__global__ void __launch_bounds__(256, 3)
cross_layer_kernel(const float4* __restrict__ x,
                   const float*  __restrict__ w,   // [3,1024]
                   const float*  __restrict__ b,   // [3,1024]
                   float4* __restrict__ out)
{
    __shared__ float  sPf[12 * 8];   // [sum_id][warp] partials
    __shared__ float  sA[RPI];       // a3 per row of current phase
    __shared__ float2 sC[8];         // (c1,c2) warp partials

    const int tid  = threadIdx.x;
    const int lane = tid & 31;
    const int wid  = tid >> 5;

    // ---- Register-resident weights / bias at this thread's feature chunk ----
    const float4 w0 = __ldg(&((const float4*)(w))[tid]);
    const float4 w1 = __ldg(&((const float4*)(w + F_DIM))[tid]);
    const float4 w2 = __ldg(&((const float4*)(w + 2 * F_DIM))[tid]);
    const float4 b0 = __ldg(&((const float4*)(b))[tid]);
    const float4 b1 = __ldg(&((const float4*)(b + F_DIM))[tid]);
    const float4 b2 = __ldg(&((const float4*)(b + 2 * F_DIM))[tid]);

    float4 b01, B;
    b01.x = b0.x + b1.x;  b01.y = b0.y + b1.y;
    b01.z = b0.z + b1.z;  b01.w = b0.w + b1.w;
    B.x = b01.x + b2.x;   B.y = b01.y + b2.y;
    B.z = b01.z + b2.z;   B.w = b01.w + b2.w;

    // ---- c1 = dot(b0,w1), c2 = dot(b0+b1,w2): batched 2-scalar butterfly ----
    {
        float q = pair_step(dot4(b0, w1), dot4(b01, w2), 16, lane);
#pragma unroll
        for (int o = 8; o; o >>= 1) q += __shfl_xor_sync(FULL, q, o);
        // lanes with bit4==0 hold c1-partial, bit4==1 hold c2-partial
        if (lane == 0)  sC[wid].x = q;
        if (lane == 16) sC[wid].y = q;
    }
    __syncthreads();
    float c1 = 0.0f, c2 = 0.0f;
#pragma unroll
    for (int i = 0; i < 8; i++) { float2 v = sC[i]; c1 += v.x; c2 += v.y; }

    // ---- Load first 4 rows (front-batched LDG.128) ----
    const size_t  base = (size_t)blockIdx.x * ROWS_PER_BLOCK * F4 + tid;
    const float4* __restrict__ xp = x + base;
    float4*       __restrict__ op = out + base;

    float4 xr[RPI], xn[RPI];
#pragma unroll
    for (int r = 0; r < RPI; r++) xr[r] = __ldg(xp + r * F4);

#pragma unroll
    for (int it = 0; it < 2; it++) {
        // Prefetch next phase's rows before the reduction latency chain.
        if (it == 0) {
#pragma unroll
            for (int r = 0; r < RPI; r++) xn[r] = __ldg(xp + (RPI + r) * F4);
        }

        // Per-thread partials: 12 scalars (3 dots x 4 rows).
        float p[12];
#pragma unroll
        for (int r = 0; r < RPI; r++) {
            p[3 * r + 0] = dot4(xr[r], w0);
            p[3 * r + 1] = dot4(xr[r], w1);
            p[3 * r + 2] = dot4(xr[r], w2);
        }

        // Batched butterfly: 13 SHFLs reduce all 12 scalars across the warp.
        float u0 = pair_step(p[0],  p[1],  16, lane);
        float u1 = pair_step(p[2],  p[3],  16, lane);
        float u2 = pair_step(p[4],  p[5],  16, lane);
        float u3 = pair_step(p[6],  p[7],  16, lane);
        float u4 = pair_step(p[8],  p[9],  16, lane);
        float u5 = pair_step(p[10], p[11], 16, lane);
        float t0 = pair_step(u0, u1, 8, lane);
        float t1 = pair_step(u2, u3, 8, lane);
        float t2 = pair_step(u4, u5, 8, lane);
        float s0 = pair_step(t0, t1, 4, lane);
        float s1 = t2 + __shfl_xor_sync(FULL, t2, 4);
        float q  = pair_step(s0, s1, 2, lane);
        q += __shfl_xor_sync(FULL, q, 1);

        // Lane -> sum_id mapping (from the pairing tree above):
        //   b1==0: id = 4*b2 + 2*b3 + b4   (ids 0..7)
        //   b1==1: id = 8 + 2*b3 + b4      (ids 8..11, b2 is replication)
        const int b4 = (lane >> 4) & 1, b3 = (lane >> 3) & 1;
        const int b2 = (lane >> 2) & 1, b1 = (lane >> 1) & 1, b0v = lane & 1;
        const int  id     = b1 ? (8 + 2 * b3 + b4) : (4 * b2 + 2 * b3 + b4);
        const bool writer = (b0v == 0) && (b1 == 0 || b2 == 0);
        if (writer) sPf[id * 8 + wid] = q;
        __syncthreads();

        // Stage 2 (warp 0): sum 8 warp-partials per id, then a3 per row.
        if (wid == 0) {
            float dsum = 0.0f;
            if (lane < 12) {
                const float4* pp = (const float4*)(sPf + lane * 8);
                float4 aa = pp[0], bb = pp[1];
                dsum = ((aa.x + aa.y) + (aa.z + aa.w))
                     + ((bb.x + bb.y) + (bb.z + bb.w));
            }
            float d0 = __shfl_sync(FULL, dsum, (3 * lane + 0) & 31);
            float d1 = __shfl_sync(FULL, dsum, (3 * lane + 1) & 31);
            float d2 = __shfl_sync(FULL, dsum, (3 * lane + 2) & 31);
            if (lane < RPI) {
                const float a1v = 1.0f + d0;
                const float s1v = fmaf(a1v, d1, c1);
                const float a2v = a1v + s1v;
                const float s2v = fmaf(a2v, d2, c2);
                sA[lane] = a2v + s2v;
            }
        }
        __syncthreads();

        // Epilogue: out = x0 * a3 + B.
#pragma unroll
        for (int r = 0; r < RPI; r++) {
            const float a3 = sA[r];
            float4 o;
            o.x = fmaf(xr[r].x, a3, B.x);
            o.y = fmaf(xr[r].y, a3, B.y);
            o.z = fmaf(xr[r].z, a3, B.z);
            o.w = fmaf(xr[r].w, a3, B.w);
            op[(it * RPI + r) * F4] = o;
        }

#pragma unroll
        for (int r = 0; r < RPI; r++) xr[r] = xn[r];
    }
}

extern "C" void kernel_launch(void* const* d_in, const int* in_sizes, int n_in,
                              void* d_out, int out_size)
{
    const float4* x = (const float4*)d_in[0];
    const float*  w = (const float*)d_in[1];   // [3,1024,1]
    const float*  b = (const float*)d_in[2];   // [3,1024,1]
    float4* out = (float4*)d_out;

    const int n_rows = in_sizes[0] / F_DIM;                          // 16384
    const int grid   = (n_rows + ROWS_PER_BLOCK - 1) / ROWS_PER_BLOCK; // 2048

    cross_layer_kernel<<<grid, 256>>>(x, w, b, out);
}